// round 3
// baseline (speedup 1.0000x reference)
#include <cuda_runtime.h>
#include <cuda_fp16.h>

#define BATCH   32768
#define PIECES  32
#define NNZ     (BATCH * PIECES)
#define FT      512
#define NF      768
#define CHUNK   128              // output channels per chunk
#define NCHUNK  (FT / CHUNK)     // 4
#define ROWB    (CHUNK * 2)      // bytes per feature row in smem (fp16) = 256
#define NBLK    37               // blocks per chunk: 4*37 = 148 = #SMs

// ---------------- device scratch (no allocations allowed) ----------------
__device__ __half g_Wt[NF * FT];          // transposed fp16 weights [feat][out]
__device__ int    g_pack[NNZ];            // stm col | nstm col << 10
__device__ __half g_valh[NNZ];            // values in fp16 (general path)
__device__ int    g_allones;              // 1 if all values == 1.0f
__device__ float  g_partial[NCHUNK * BATCH];

// ---------------- prep: transpose ft_w [512,768] -> [768,512] fp16 -------
__global__ void prep_w(const float* __restrict__ ft_w) {
    int i = blockIdx.x * blockDim.x + threadIdx.x;
    if (i == 0) g_allones = 1;           // reset flag each call (stream-ordered)
    if (i < NF * FT) {
        int f = i >> 9;        // feature 0..767
        int k = i & 511;       // out channel 0..511
        g_Wt[i] = __float2half(ft_w[k * NF + f]);
    }
}

// ---------------- prep: pack columns, convert values ---------------------
// Index dtype sniffed at runtime: row 0 is repeat(arange(B), 32), so an int32
// view has [64]=1,[65]=0 iff little-endian int64, [64]=2,[65]=2 iff int32.
__global__ void prep_idx(const int* __restrict__ stm32,
                         const int* __restrict__ nstm32,
                         const float* __restrict__ vals) {
    const bool is64 = (stm32[64] == 1 && stm32[65] == 0);
    int i = blockIdx.x * blockDim.x + threadIdx.x;
    if (i < NNZ) {
        int cs, cn;
        if (is64) {
            cs = stm32[2 * (NNZ + i)];      // low word of int64 col
            cn = nstm32[2 * (NNZ + i)];
        } else {
            cs = stm32[NNZ + i];
            cn = nstm32[NNZ + i];
        }
        g_pack[i] = cs | (cn << 10);
        float v = vals[i];
        g_valh[i] = __float2half(v);
        if (v != 1.0f) g_allones = 0;       // benign race: only writes 0
    }
}

// ---------------- main: gather-accumulate from smem-resident W chunk -----
// Half-warp split: lanes 0-15 gather the STM row, lanes 16-31 the NSTM row,
// each lane loads 16B (8 channels) via LDS.128. One SHFL broadcast per piece.
__global__ void __launch_bounds__(512, 1)
main_k(const float* __restrict__ ft_b, const float* __restrict__ out_w) {
    extern __shared__ __half sW[];   // [NF][CHUNK] fp16 = 192 KB
    const int chunk = blockIdx.y;
    const int tid = threadIdx.x;

    // stage W chunk: 12288 uint4 copies
    {
        uint4* dst = (uint4*)sW;
        for (int i = tid; i < NF * (CHUNK / 8); i += blockDim.x) {
            int f = i >> 4;          // feature
            int q = i & 15;          // 16B quad within row
            dst[i] = ((const uint4*)(g_Wt + f * FT + chunk * CHUNK))[q];
        }
    }
    __syncthreads();

    const int warp = tid >> 5, lane = tid & 31;
    const int gw = blockIdx.x * (blockDim.x >> 5) + warp;
    const int stride = gridDim.x * (blockDim.x >> 5);

    const int side = lane >> 4;          // 0 = stm, 1 = nstm
    const int li   = lane & 15;          // lane within half
    const int sh   = side * 10;          // bit shift to extract my column
    const char* sbase = (const char*)sW + li * 16;

    // epilogue coefficients: this lane owns 8 channels of one side
    const int ch = chunk * CHUNK + li * 8;
    const float4 b0 = *(const float4*)(ft_b + ch);
    const float4 b1 = *(const float4*)(ft_b + ch + 4);
    const float4 w0 = *(const float4*)(out_w + side * FT + ch);
    const float4 w1 = *(const float4*)(out_w + side * FT + ch + 4);

    const __half2 hz = __float2half2_rn(0.f);
    const int ones = g_allones;          // uniform branch

    for (int b = gw; b < BATCH; b += stride) {
        const int base = b * PIECES + lane;
        const int pk = g_pack[base];

        // split accumulator banks (even/odd pieces) to reduce fp16 walk
        __half2 a0 = hz, a1 = hz, a2 = hz, a3 = hz;   // even pieces
        __half2 c0 = hz, c1 = hz, c2 = hz, c3 = hz;   // odd pieces

        if (ones) {
            #pragma unroll
            for (int j = 0; j < PIECES; j++) {
                int p = __shfl_sync(0xffffffffu, pk, j);
                const uint4 d = *(const uint4*)(sbase + (((p >> sh) & 1023) << 8));
                __half2 h0 = *(__half2*)&d.x, h1 = *(__half2*)&d.y;
                __half2 h2 = *(__half2*)&d.z, h3 = *(__half2*)&d.w;
                if (j & 1) {
                    c0 = __hadd2(c0, h0); c1 = __hadd2(c1, h1);
                    c2 = __hadd2(c2, h2); c3 = __hadd2(c3, h3);
                } else {
                    a0 = __hadd2(a0, h0); a1 = __hadd2(a1, h1);
                    a2 = __hadd2(a2, h2); a3 = __hadd2(a3, h3);
                }
            }
        } else {
            const unsigned vv = (unsigned)__half_as_ushort(g_valh[base]);
            #pragma unroll
            for (int j = 0; j < PIECES; j++) {
                int p = __shfl_sync(0xffffffffu, pk, j);
                unsigned vj = __shfl_sync(0xffffffffu, vv, j);
                __half2 v2 = __half2half2(__ushort_as_half((unsigned short)vj));
                const uint4 d = *(const uint4*)(sbase + (((p >> sh) & 1023) << 8));
                __half2 h0 = *(__half2*)&d.x, h1 = *(__half2*)&d.y;
                __half2 h2 = *(__half2*)&d.z, h3 = *(__half2*)&d.w;
                if (j & 1) {
                    c0 = __hfma2(h0, v2, c0); c1 = __hfma2(h1, v2, c1);
                    c2 = __hfma2(h2, v2, c2); c3 = __hfma2(h3, v2, c3);
                } else {
                    a0 = __hfma2(h0, v2, a0); a1 = __hfma2(h1, v2, a1);
                    a2 = __hfma2(h2, v2, a2); a3 = __hfma2(h3, v2, a3);
                }
            }
        }

        // combine banks in fp32
        float2 f0a = __half22float2(a0), f0c = __half22float2(c0);
        float2 f1a = __half22float2(a1), f1c = __half22float2(c1);
        float2 f2a = __half22float2(a2), f2c = __half22float2(c2);
        float2 f3a = __half22float2(a3), f3c = __half22float2(c3);

        float r = 0.f;
        r += __saturatef(f0a.x + f0c.x + b0.x) * w0.x;
        r += __saturatef(f0a.y + f0c.y + b0.y) * w0.y;
        r += __saturatef(f1a.x + f1c.x + b0.z) * w0.z;
        r += __saturatef(f1a.y + f1c.y + b0.w) * w0.w;
        r += __saturatef(f2a.x + f2c.x + b1.x) * w1.x;
        r += __saturatef(f2a.y + f2c.y + b1.y) * w1.y;
        r += __saturatef(f3a.x + f3c.x + b1.z) * w1.z;
        r += __saturatef(f3a.y + f3c.y + b1.w) * w1.w;

        #pragma unroll
        for (int d = 16; d > 0; d >>= 1)
            r += __shfl_xor_sync(0xffffffffu, r, d);

        if (lane == 0) g_partial[chunk * BATCH + b] = r;
    }
}

// ---------------- epilogue: sum partials + sigmoid -----------------------
__global__ void epi_k(const float* __restrict__ out_b, float* __restrict__ out) {
    int b = blockIdx.x * blockDim.x + threadIdx.x;
    if (b < BATCH) {
        float s = out_b[0];
        #pragma unroll
        for (int c = 0; c < NCHUNK; c++) s += g_partial[c * BATCH + b];
        out[b] = 1.f / (1.f + __expf(-s));
    }
}

// ---------------- launch --------------------------------------------------
extern "C" void kernel_launch(void* const* d_in, const int* in_sizes, int n_in,
                              void* d_out, int out_size) {
    // Fixed leading inputs (dict order): stm_indices, nstm_indices, values.
    const int*   stm  = (const int*)d_in[0];   // [2, NNZ] int32 or int64 (sniffed)
    const int*   nstm = (const int*)d_in[1];
    const float* vals = (const float*)d_in[2];

    // Trailing inputs mapped by element count ("size" may or may not be a
    // real buffer). out_b is the LAST size-1 entry (dict order: size < out_b).
    const float* ft_w  = 0;
    const float* ft_b  = 0;
    const float* out_w = 0;
    const float* out_b = 0;
    for (int i = 3; i < n_in; i++) {
        int s = in_sizes[i];
        if      (s == NF * FT) ft_w  = (const float*)d_in[i];
        else if (s == FT)      ft_b  = (const float*)d_in[i];
        else if (s == 2 * FT)  out_w = (const float*)d_in[i];
        else if (s == 1)       out_b = (const float*)d_in[i];  // last wins
    }
    float* out = (float*)d_out;                  // [B, 1] float32

    prep_w<<<(NF * FT + 255) / 256, 256>>>(ft_w);
    prep_idx<<<(NNZ + 255) / 256, 256>>>(stm, nstm, vals);

    const int SMEM = NF * CHUNK * 2;   // 192 KB
    cudaFuncSetAttribute(main_k, cudaFuncAttributeMaxDynamicSharedMemorySize, SMEM);
    main_k<<<dim3(NBLK, NCHUNK), 512, SMEM>>>(ft_b, out_w);

    epi_k<<<(BATCH + 127) / 128, 128>>>(out_b, out);
}

// round 4
// speedup vs baseline: 1.6092x; 1.6092x over previous
#include <cuda_runtime.h>
#include <cuda_fp16.h>

#define BATCH   32768
#define PIECES  32
#define NNZ     (BATCH * PIECES)
#define FT      512
#define NF      768
#define CHUNK   128              // output channels per chunk
#define NCHUNK  (FT / CHUNK)     // 4
#define ROWB    (CHUNK * 2)      // bytes per feature row in smem (fp16) = 256
#define NBLK    37               // blocks per chunk: 4*37 = 148 = #SMs

// ---------------- device scratch (no allocations allowed) ----------------
__device__ __half g_Wt[NF * FT];          // transposed fp16 weights [feat][out]
__device__ int    g_pack[NNZ];            // stm col | nstm col << 10
__device__ __half g_valh[NNZ];            // values in fp16 (general path)
__device__ int    g_allones;              // 1 if all values == 1.0f
__device__ float  g_partial[NCHUNK * BATCH];

// ---------------- prep: transpose ft_w [512,768] -> [768,512] fp16 -------
__global__ void prep_w(const float* __restrict__ ft_w) {
    int i = blockIdx.x * blockDim.x + threadIdx.x;
    if (i == 0) g_allones = 1;           // reset flag each call (stream-ordered)
    if (i < NF * FT) {
        int f = i >> 9;        // feature 0..767
        int k = i & 511;       // out channel 0..511
        g_Wt[i] = __float2half(ft_w[k * NF + f]);
    }
}

// ---------------- prep: pack columns, convert values ---------------------
// Index dtype sniffed at runtime: row 0 is repeat(arange(B), 32), so an int32
// view has [64]=1,[65]=0 iff little-endian int64, [64]=2,[65]=2 iff int32.
__global__ void prep_idx(const int* __restrict__ stm32,
                         const int* __restrict__ nstm32,
                         const float* __restrict__ vals) {
    const bool is64 = (stm32[64] == 1 && stm32[65] == 0);
    int i = blockIdx.x * blockDim.x + threadIdx.x;
    if (i < NNZ) {
        int cs, cn;
        if (is64) {
            cs = stm32[2 * (NNZ + i)];      // low word of int64 col
            cn = nstm32[2 * (NNZ + i)];
        } else {
            cs = stm32[NNZ + i];
            cn = nstm32[NNZ + i];
        }
        g_pack[i] = cs | (cn << 10);
        float v = vals[i];
        g_valh[i] = __float2half(v);
        if (v != 1.0f) g_allones = 0;       // benign race: only writes 0
    }
}

// ---------------- main: gather-accumulate from smem-resident W chunk -----
// R2 load shape (warp-wide uint2 row reads), one packed SHFL per piece.
__global__ void __launch_bounds__(512, 1)
main_k(const float* __restrict__ ft_b, const float* __restrict__ out_w) {
    extern __shared__ __half sW[];   // [NF][CHUNK] fp16 = 192 KB
    const int chunk = blockIdx.y;
    const int tid = threadIdx.x;

    // stage W chunk: 12288 uint4 copies
    {
        uint4* dst = (uint4*)sW;
        for (int i = tid; i < NF * (CHUNK / 8); i += blockDim.x) {
            int f = i >> 4;          // feature
            int q = i & 15;          // 16B quad within row
            dst[i] = ((const uint4*)(g_Wt + f * FT + chunk * CHUNK))[q];
        }
    }
    __syncthreads();

    const int warp = tid >> 5, lane = tid & 31;
    const int gw = blockIdx.x * (blockDim.x >> 5) + warp;
    const int stride = gridDim.x * (blockDim.x >> 5);

    const char* sbase = (const char*)sW + lane * 8;   // lane's 8B within a row

    // loop-invariant epilogue coefficients for this lane's 4 channels
    const int ch = chunk * CHUNK + lane * 4;
    const float4 bb = *(const float4*)(ft_b + ch);
    const float4 ws = *(const float4*)(out_w + ch);
    const float4 wn = *(const float4*)(out_w + FT + ch);

    const __half2 hz = __float2half2_rn(0.f);
    const int ones = g_allones;          // uniform branch

    for (int b = gw; b < BATCH; b += stride) {
        const int base = b * PIECES + lane;
        const int pk = g_pack[base];

        // split accumulator banks (even/odd pieces) to reduce fp16 walk
        __half2 aS0a = hz, aS1a = hz, aS0b = hz, aS1b = hz;
        __half2 aN0a = hz, aN1a = hz, aN0b = hz, aN1b = hz;

        if (ones) {
            #pragma unroll
            for (int j = 0; j < PIECES; j++) {
                int p = __shfl_sync(0xffffffffu, pk, j);
                uint2 dS = *(const uint2*)(sbase + ((p & 1023) << 8));
                uint2 dN = *(const uint2*)(sbase + (((p >> 10) & 1023) << 8));
                __half2 s0 = *(__half2*)&dS.x;
                __half2 s1 = *(__half2*)&dS.y;
                __half2 n0 = *(__half2*)&dN.x;
                __half2 n1 = *(__half2*)&dN.y;
                if (j & 1) {
                    aS0b = __hadd2(aS0b, s0); aS1b = __hadd2(aS1b, s1);
                    aN0b = __hadd2(aN0b, n0); aN1b = __hadd2(aN1b, n1);
                } else {
                    aS0a = __hadd2(aS0a, s0); aS1a = __hadd2(aS1a, s1);
                    aN0a = __hadd2(aN0a, n0); aN1a = __hadd2(aN1a, n1);
                }
            }
        } else {
            const unsigned vv = (unsigned)__half_as_ushort(g_valh[base]);
            #pragma unroll
            for (int j = 0; j < PIECES; j++) {
                int p = __shfl_sync(0xffffffffu, pk, j);
                unsigned vj = __shfl_sync(0xffffffffu, vv, j);
                __half2 v2 = __half2half2(__ushort_as_half((unsigned short)vj));
                uint2 dS = *(const uint2*)(sbase + ((p & 1023) << 8));
                uint2 dN = *(const uint2*)(sbase + (((p >> 10) & 1023) << 8));
                __half2 s0 = *(__half2*)&dS.x;
                __half2 s1 = *(__half2*)&dS.y;
                __half2 n0 = *(__half2*)&dN.x;
                __half2 n1 = *(__half2*)&dN.y;
                if (j & 1) {
                    aS0b = __hfma2(s0, v2, aS0b); aS1b = __hfma2(s1, v2, aS1b);
                    aN0b = __hfma2(n0, v2, aN0b); aN1b = __hfma2(n1, v2, aN1b);
                } else {
                    aS0a = __hfma2(s0, v2, aS0a); aS1a = __hfma2(s1, v2, aS1a);
                    aN0a = __hfma2(n0, v2, aN0a); aN1a = __hfma2(n1, v2, aN1a);
                }
            }
        }

        // combine banks in fp32
        float2 fS0a = __half22float2(aS0a), fS0b = __half22float2(aS0b);
        float2 fS1a = __half22float2(aS1a), fS1b = __half22float2(aS1b);
        float2 fN0a = __half22float2(aN0a), fN0b = __half22float2(aN0b);
        float2 fN1a = __half22float2(aN1a), fN1b = __half22float2(aN1b);

        float s0 = fS0a.x + fS0b.x, s1 = fS0a.y + fS0b.y;
        float s2 = fS1a.x + fS1b.x, s3 = fS1a.y + fS1b.y;
        float n0 = fN0a.x + fN0b.x, n1 = fN0a.y + fN0b.y;
        float n2 = fN1a.x + fN1b.x, n3 = fN1a.y + fN1b.y;

        float r = 0.f;
        r += __saturatef(s0 + bb.x) * ws.x;
        r += __saturatef(s1 + bb.y) * ws.y;
        r += __saturatef(s2 + bb.z) * ws.z;
        r += __saturatef(s3 + bb.w) * ws.w;
        r += __saturatef(n0 + bb.x) * wn.x;
        r += __saturatef(n1 + bb.y) * wn.y;
        r += __saturatef(n2 + bb.z) * wn.z;
        r += __saturatef(n3 + bb.w) * wn.w;

        #pragma unroll
        for (int d = 16; d > 0; d >>= 1)
            r += __shfl_xor_sync(0xffffffffu, r, d);

        if (lane == 0) g_partial[chunk * BATCH + b] = r;
    }
}

// ---------------- epilogue: sum partials + sigmoid -----------------------
__global__ void epi_k(const float* __restrict__ out_b, float* __restrict__ out) {
    int b = blockIdx.x * blockDim.x + threadIdx.x;
    if (b < BATCH) {
        float s = out_b[0];
        #pragma unroll
        for (int c = 0; c < NCHUNK; c++) s += g_partial[c * BATCH + b];
        out[b] = 1.f / (1.f + __expf(-s));
    }
}

// ---------------- launch --------------------------------------------------
extern "C" void kernel_launch(void* const* d_in, const int* in_sizes, int n_in,
                              void* d_out, int out_size) {
    // Fixed leading inputs (dict order): stm_indices, nstm_indices, values.
    const int*   stm  = (const int*)d_in[0];   // [2, NNZ] int32 or int64 (sniffed)
    const int*   nstm = (const int*)d_in[1];
    const float* vals = (const float*)d_in[2];

    // Trailing inputs mapped by element count ("size" may or may not be a
    // real buffer). out_b is the LAST size-1 entry (dict order: size < out_b).
    const float* ft_w  = 0;
    const float* ft_b  = 0;
    const float* out_w = 0;
    const float* out_b = 0;
    for (int i = 3; i < n_in; i++) {
        int s = in_sizes[i];
        if      (s == NF * FT) ft_w  = (const float*)d_in[i];
        else if (s == FT)      ft_b  = (const float*)d_in[i];
        else if (s == 2 * FT)  out_w = (const float*)d_in[i];
        else if (s == 1)       out_b = (const float*)d_in[i];  // last wins
    }
    float* out = (float*)d_out;                  // [B, 1] float32

    prep_w<<<(NF * FT + 255) / 256, 256>>>(ft_w);
    prep_idx<<<(NNZ + 255) / 256, 256>>>(stm, nstm, vals);

    const int SMEM = NF * CHUNK * 2;   // 192 KB
    cudaFuncSetAttribute(main_k, cudaFuncAttributeMaxDynamicSharedMemorySize, SMEM);
    main_k<<<dim3(NBLK, NCHUNK), 512, SMEM>>>(ft_b, out_w);

    epi_k<<<(BATCH + 255) / 256, 256>>>(out_b, out);
}